// round 1
// baseline (speedup 1.0000x reference)
#include <cuda_runtime.h>
#include <cstdint>

// ============================================================================
// ResidualBlockWithPointsBase: sparse conv (gather-GEMM-scatter) x2 with BN/ReLU
//   y1 = conv(x, W1);                    BN1 stats; fold -> scale/shift
//   y2 = conv(relu(bn1(y1)), W2);        BN2 stats; fold -> scale/shift
//   out = relu(bn2(y2) + x)
// Channel layout in scratch is PACKED: float2 at [row][l] = (ch l, ch l+32)
// ============================================================================

#define MAXN 100352

__device__ float2 g_y1[MAXN * 32];
__device__ float2 g_y2[MAXN * 32];
__device__ float2 g_stats[4 * 32];  // sum1[32], sumsq1[32], sum2[32], sumsq2[32]
__device__ float2 g_bn[4 * 32];     // scale1[32], shift1[32], scale2[32], shift2[32]

// ---- packed f32x2 helpers (Blackwell FFMA2 path, only reachable via PTX) ----
__device__ __forceinline__ unsigned long long pack2(float a, float b) {
    unsigned long long r;
    asm("mov.b64 %0, {%1, %2};" : "=l"(r) : "r"(__float_as_uint(a)), "r"(__float_as_uint(b)));
    return r;
}
__device__ __forceinline__ unsigned long long bcast2(float a) {
    unsigned long long r;
    asm("mov.b64 %0, {%1, %1};" : "=l"(r) : "r"(__float_as_uint(a)));
    return r;
}
__device__ __forceinline__ void ffma2(unsigned long long& d, unsigned long long a,
                                      unsigned long long b) {
    asm("fma.rn.f32x2 %0, %1, %2, %0;" : "+l"(d) : "l"(a), "l"(b));
}

// ---------------------------------------------------------------------------
// conv kernel: for offset k (blockIdx.y), edges e: y[out_idx[k,e]] += x[in_idx[k,e]] @ W[k]
// W[k] is 64x64 staged in smem as (c -> (W[c][l], W[c][l+32])) pairs.
// Each warp: 4 edges per iteration, lane owns output channels (l, l+32).
// x-broadcast across the warp via shfl; accumulate with fma.rn.f32x2.
// ---------------------------------------------------------------------------
template <bool PACKED_IN, bool BN>
__global__ __launch_bounds__(256) void conv_kernel(
    const float* __restrict__ xin,    // [N][64] when !PACKED_IN
    const float2* __restrict__ xinp,  // [N][32] packed when PACKED_IN
    const float* __restrict__ W,      // [K][64][64]
    const int* __restrict__ in_idx, const int* __restrict__ out_idx,
    float2* __restrict__ yout,        // [N][32] packed, pre-zeroed
    const float2* __restrict__ bnscale, const float2* __restrict__ bnshift, int nE) {
    __shared__ unsigned long long Wp[64][32];

    const int k = blockIdx.y;
    const float* Wk = W + (size_t)k * 4096;
    for (int i = threadIdx.x; i < 64 * 32; i += blockDim.x) {
        int c = i >> 5, l = i & 31;
        Wp[c][l] = pack2(Wk[c * 64 + l], Wk[c * 64 + l + 32]);
    }
    __syncthreads();

    const int lane = threadIdx.x & 31;
    const int warp = threadIdx.x >> 5;
    const int wpb = blockDim.x >> 5;

    float2 bs = {0.f, 0.f}, bh = {0.f, 0.f};
    if (BN) { bs = bnscale[lane]; bh = bnshift[lane]; }

    const int* ii = in_idx + (size_t)k * nE;
    const int* oi = out_idx + (size_t)k * nE;

    for (int e0 = (blockIdx.x * wpb + warp) * 4; e0 < nE; e0 += gridDim.x * wpb * 4) {
        float xa[4], xb[4];
        int og[4];
#pragma unroll
        for (int j = 0; j < 4; j++) {
            int ee = e0 + j;
            bool valid = ee < nE;
            int ig = valid ? __ldg(ii + ee) : 0;
            og[j] = valid ? __ldg(oi + ee) : -1;
            float a, b;
            if (PACKED_IN) {
                float2 t = xinp[(size_t)ig * 32 + lane];
                a = t.x; b = t.y;
            } else {
                a = xin[(size_t)ig * 64 + lane];
                b = xin[(size_t)ig * 64 + lane + 32];
            }
            if (BN) {
                a = fmaxf(fmaf(a, bs.x, bh.x), 0.f);
                b = fmaxf(fmaf(b, bs.y, bh.y), 0.f);
            }
            xa[j] = a; xb[j] = b;
        }

        unsigned long long acc[4] = {0ull, 0ull, 0ull, 0ull};  // (0.f,0.f)
#pragma unroll
        for (int c = 0; c < 64; c++) {
            unsigned long long w = Wp[c][lane];
#pragma unroll
            for (int j = 0; j < 4; j++) {
                float xc = __shfl_sync(0xffffffffu, (c < 32) ? xa[j] : xb[j], c & 31);
                ffma2(acc[j], bcast2(xc), w);
            }
        }

#pragma unroll
        for (int j = 0; j < 4; j++) {
            if (og[j] >= 0) {
                float2 v = *reinterpret_cast<float2*>(&acc[j]);
                atomicAdd(&yout[(size_t)og[j] * 32 + lane], v);  // RED.64 (sm_90+)
            }
        }
    }
}

// ---------------------------------------------------------------------------
// per-channel sum / sum-of-squares over all rows (packed layout)
// sums[0..31] = sum pairs, sums[32..63] = sumsq pairs
// ---------------------------------------------------------------------------
__global__ __launch_bounds__(256) void stats_kernel(const float2* __restrict__ y,
                                                    float2* __restrict__ sums, int n) {
    const int lane = threadIdx.x & 31;
    const int warp = threadIdx.x >> 5;
    const int wpb = blockDim.x >> 5;

    float2 s = {0.f, 0.f}, q = {0.f, 0.f};
    for (int r = blockIdx.x * wpb + warp; r < n; r += gridDim.x * wpb) {
        float2 v = y[(size_t)r * 32 + lane];
        s.x += v.x; s.y += v.y;
        q.x = fmaf(v.x, v.x, q.x);
        q.y = fmaf(v.y, v.y, q.y);
    }
    __shared__ float2 sh_s[8][32], sh_q[8][32];
    sh_s[warp][lane] = s;
    sh_q[warp][lane] = q;
    __syncthreads();
    if (warp == 0) {
        for (int i = 1; i < wpb; i++) {
            s.x += sh_s[i][lane].x; s.y += sh_s[i][lane].y;
            q.x += sh_q[i][lane].x; q.y += sh_q[i][lane].y;
        }
        atomicAdd(&sums[lane], s);
        atomicAdd(&sums[32 + lane], q);
    }
}

// fold BN into per-channel scale/shift:  y_bn = y*scale + shift
__global__ void finalize_kernel(const float2* __restrict__ sums,
                                const float* __restrict__ gamma,
                                const float* __restrict__ beta,
                                float2* __restrict__ bnout, float invN) {
    int l = threadIdx.x;  // 0..31
    float2 s = sums[l], q = sums[32 + l];
    float mx = s.x * invN, my = s.y * invN;
    float vx = fmaf(q.x, invN, -mx * mx);
    float vy = fmaf(q.y, invN, -my * my);
    float scx = gamma[l] * rsqrtf(vx + 1e-5f);
    float scy = gamma[l + 32] * rsqrtf(vy + 1e-5f);
    bnout[l] = make_float2(scx, scy);
    bnout[32 + l] = make_float2(beta[l] - mx * scx, beta[l + 32] - my * scy);
}

// out = relu(bn2(y2) + x), packed scratch -> standard [N][64] output
__global__ __launch_bounds__(256) void final_kernel(const float2* __restrict__ y2,
                                                    const float* __restrict__ x,
                                                    const float2* __restrict__ bn,
                                                    float* __restrict__ out, int n32) {
    int i = blockIdx.x * blockDim.x + threadIdx.x;
    if (i >= n32) return;
    int l = i & 31, row = i >> 5;
    float2 v = y2[i];
    float2 sc = bn[l], sh = bn[32 + l];
    out[row * 64 + l]      = fmaxf(fmaf(v.x, sc.x, sh.x) + x[row * 64 + l], 0.f);
    out[row * 64 + l + 32] = fmaxf(fmaf(v.y, sc.y, sh.y) + x[row * 64 + l + 32], 0.f);
}

// ---------------------------------------------------------------------------
extern "C" void kernel_launch(void* const* d_in, const int* in_sizes, int n_in,
                              void* d_out, int out_size) {
    const float* x      = (const float*)d_in[0];
    // d_in[1] = norm_points (unused by reference math)
    const float* W1     = (const float*)d_in[2];
    const float* gamma1 = (const float*)d_in[3];
    const float* beta1  = (const float*)d_in[4];
    const float* W2     = (const float*)d_in[5];
    const float* gamma2 = (const float*)d_in[6];
    const float* beta2  = (const float*)d_in[7];
    const int* in_idx   = (const int*)d_in[8];
    const int* out_idx  = (const int*)d_in[9];

    const int N = in_sizes[0] / 64;          // 100000
    const int K = in_sizes[2] / (64 * 64);   // 27

    float2 *y1, *y2, *stats, *bn;
    cudaGetSymbolAddress((void**)&y1, g_y1);
    cudaGetSymbolAddress((void**)&y2, g_y2);
    cudaGetSymbolAddress((void**)&stats, g_stats);
    cudaGetSymbolAddress((void**)&bn, g_bn);

    cudaMemsetAsync(y1, 0, (size_t)N * 32 * sizeof(float2));
    cudaMemsetAsync(y2, 0, (size_t)N * 32 * sizeof(float2));
    cudaMemsetAsync(stats, 0, 4 * 32 * sizeof(float2));

    dim3 cgrid(40, K);
    const float invN = 1.0f / (float)N;

    // layer 1
    conv_kernel<false, false><<<cgrid, 256>>>(x, nullptr, W1, in_idx, out_idx, y1,
                                              nullptr, nullptr, N);
    stats_kernel<<<256, 256>>>(y1, stats, N);
    finalize_kernel<<<1, 32>>>(stats, gamma1, beta1, bn, invN);

    // layer 2 (BN1+ReLU folded into the gather)
    conv_kernel<true, true><<<cgrid, 256>>>(nullptr, y1, W2, in_idx, out_idx, y2,
                                            bn, bn + 32, N);
    stats_kernel<<<256, 256>>>(y2, stats + 64, N);
    finalize_kernel<<<1, 32>>>(stats + 64, gamma2, beta2, bn + 64, invN);

    // epilogue: BN2 + residual + ReLU
    final_kernel<<<(N * 32 + 255) / 256, 256>>>(y2, x, bn + 64, (float*)d_out, N * 32);
}

// round 2
// speedup vs baseline: 1.4688x; 1.4688x over previous
#include <cuda_runtime.h>
#include <cstdint>

// ============================================================================
// ResidualBlockWithPointsBase: sparse conv (gather-GEMM-scatter) x2 with BN/ReLU
//   y1 = conv(x, W1);                    BN1 stats -> fold scale/shift
//   y2 = conv(relu(bn1(y1)), W2);        BN2 stats -> fold scale/shift
//   out = relu(bn2(y2) + x)
// Scratch y layout PACKED: float2 at [row][l] = (ch l, ch l+32); viewed as
// linear float[64] memory order: mem[2l]=ch l, mem[2l+1]=ch l+32.
// BN scale/shift are stored in that same memory order so conv staging reads
// them linearly.
//
// conv v2 (crossbar-optimized):
//   - warp processes 16 edges/iter
//   - gather edge rows with LDG.128 (2 edges per instr), BN+ReLU fold, STS.128
//   - inner product via fma.rn.f32x2 paired over INPUT channels
//     (a = two consecutive mem floats; horizontal add at the end)
//   - x read back via uniform-address LDS.128 broadcast (1 wavefront each)
//   - W smem swept once per 16 edges (register-cached per 2-pair chunk)
//   - scatter: one coalesced RED.64 (float2) per edge
// ============================================================================

#define MAXN 100352
typedef unsigned long long ull;

__device__ float2 g_y1[MAXN * 32];
__device__ float2 g_y2[MAXN * 32];
__device__ float2 g_stats[4 * 32];  // sum1[32], sumsq1[32], sum2[32], sumsq2[32]
__device__ float2 g_bn[4 * 32];     // scale1,shift1,scale2,shift2 (mem order)

__device__ __forceinline__ ull pack2(float a, float b) {
    ull r;
    asm("mov.b64 %0, {%1, %2};" : "=l"(r) : "r"(__float_as_uint(a)), "r"(__float_as_uint(b)));
    return r;
}
__device__ __forceinline__ void unpack2(ull v, float& a, float& b) {
    unsigned x, y;
    asm("mov.b64 {%0, %1}, %2;" : "=r"(x), "=r"(y) : "l"(v));
    a = __uint_as_float(x);
    b = __uint_as_float(y);
}
__device__ __forceinline__ void ffma2(ull& d, ull a, ull b) {
    asm("fma.rn.f32x2 %0, %1, %2, %0;" : "+l"(d) : "l"(a), "l"(b));
}

// ---------------------------------------------------------------------------
// conv v2. blockIdx.y = k. Input viewed as linear float[N*64] (mem order).
// PACKED_IN: mem float i maps to channel (i even: i/2, i odd: i/2+32);
//            W pair p then uses rows (p, p+32). Linear input: rows (2p, 2p+1).
// Output: lane owns out channels (lane, lane+32) -> packed float2 scatter.
// ---------------------------------------------------------------------------
template <bool PACKED_IN, bool BN>
__global__ __launch_bounds__(256, 1) void conv2_kernel(
    const float* __restrict__ xin,   // [N*64] mem order
    const float* __restrict__ W,     // [K][64][64]
    const int* __restrict__ in_idx, const int* __restrict__ out_idx,
    float2* __restrict__ yout,       // [N][32] packed, pre-zeroed
    const float* __restrict__ bnscale, const float* __restrict__ bnshift, int nE) {
    __shared__ ulonglong2 Wsm[32][32];     // [pair p][out lane l] = (b_l, b_{l+32}), 16KB
    __shared__ float4 xstage[8][16][16];   // [warp][edge][16B chunk], 32KB

    const int tid = threadIdx.x;
    const int lane = tid & 31;
    const int warp = tid >> 5;
    const int k = blockIdx.y;
    const float* Wk = W + (size_t)k * 4096;

    // Build W smem: pair p covers mem floats (2p, 2p+1) -> rows (r0, r1).
    for (int i = tid; i < 1024; i += 256) {
        int p = i >> 5, ln = i & 31;
        int r0 = PACKED_IN ? p : 2 * p;
        int r1 = PACKED_IN ? p + 32 : 2 * p + 1;
        ulonglong2 w;
        w.x = pack2(Wk[r0 * 64 + ln], Wk[r1 * 64 + ln]);
        w.y = pack2(Wk[r0 * 64 + ln + 32], Wk[r1 * 64 + ln + 32]);
        Wsm[p][ln] = w;
    }
    __syncthreads();

    // BN params for this lane's staging chunk (4 consecutive mem floats).
    float4 s4 = {0, 0, 0, 0}, h4 = {0, 0, 0, 0};
    if (BN) {
        s4 = reinterpret_cast<const float4*>(bnscale)[lane & 15];
        h4 = reinterpret_cast<const float4*>(bnshift)[lane & 15];
    }

    const int* ii = in_idx + (size_t)k * nE;
    const int* oi = out_idx + (size_t)k * nE;
    const int wpb = 8;

    for (int e0 = (blockIdx.x * wpb + warp) * 16; e0 < nE; e0 += gridDim.x * wpb * 16) {
        // lanes 0..15 load in_idx for edges e0..e0+15, lanes 16..31 load out_idx
        int e_mine = e0 + (lane & 15);
        int idx_mine = 0;
        if (e_mine < nE) idx_mine = (lane < 16) ? __ldg(ii + e_mine) : __ldg(oi + e_mine);

        __syncwarp();  // WAR: previous iter's compute reads done before restage

        // Gather + (BN+ReLU) + stage: 2 edges per LDG.128
#pragma unroll
        for (int j2 = 0; j2 < 8; j2++) {
            int r0 = __shfl_sync(0xffffffffu, idx_mine, 2 * j2);
            int r1 = __shfl_sync(0xffffffffu, idx_mine, 2 * j2 + 1);
            int rr = (lane < 16) ? r0 : r1;
            float4 xv = *reinterpret_cast<const float4*>(xin + (size_t)rr * 64 + (lane & 15) * 4);
            if (BN) {
                xv.x = fmaxf(fmaf(xv.x, s4.x, h4.x), 0.f);
                xv.y = fmaxf(fmaf(xv.y, s4.y, h4.y), 0.f);
                xv.z = fmaxf(fmaf(xv.z, s4.z, h4.z), 0.f);
                xv.w = fmaxf(fmaf(xv.w, s4.w, h4.w), 0.f);
            }
            xstage[warp][2 * j2 + (lane >> 4)][lane & 15] = xv;
        }
        __syncwarp();

        // Accumulate: acc0 -> out ch lane, acc1 -> out ch lane+32.
        // Each acc holds (partial_even, partial_odd) over input pairs.
        ull acc0[16], acc1[16];
#pragma unroll
        for (int e = 0; e < 16; e++) { acc0[e] = 0ull; acc1[e] = 0ull; }

#pragma unroll
        for (int pc = 0; pc < 16; pc++) {
            ulonglong2 w0 = Wsm[2 * pc][lane];      // pair 2pc
            ulonglong2 w1 = Wsm[2 * pc + 1][lane];  // pair 2pc+1
#pragma unroll
            for (int e = 0; e < 16; e++) {
                float4 xv = xstage[warp][e][pc];    // uniform-address broadcast
                ull a0 = pack2(xv.x, xv.y);
                ull a1 = pack2(xv.z, xv.w);
                ffma2(acc0[e], a0, w0.x);
                ffma2(acc1[e], a0, w0.y);
                ffma2(acc0[e], a1, w1.x);
                ffma2(acc1[e], a1, w1.y);
            }
        }

        // Horizontal add + coalesced packed scatter
#pragma unroll
        for (int e = 0; e < 16; e++) {
            if (e0 + e < nE) {
                int og = __shfl_sync(0xffffffffu, idx_mine, 16 + e);
                float a, b, c, d;
                unpack2(acc0[e], a, b);
                unpack2(acc1[e], c, d);
                float2 r = make_float2(a + b, c + d);
                atomicAdd(&yout[(size_t)og * 32 + lane], r);  // RED.64
            }
        }
    }
}

// ---------------------------------------------------------------------------
// per-channel sum / sum-of-squares over all rows (packed layout)
// ---------------------------------------------------------------------------
__global__ __launch_bounds__(256) void stats_kernel(const float2* __restrict__ y,
                                                    float2* __restrict__ sums, int n) {
    const int lane = threadIdx.x & 31;
    const int warp = threadIdx.x >> 5;
    const int wpb = blockDim.x >> 5;

    float2 s = {0.f, 0.f}, q = {0.f, 0.f};
    for (int r = blockIdx.x * wpb + warp; r < n; r += gridDim.x * wpb) {
        float2 v = y[(size_t)r * 32 + lane];
        s.x += v.x; s.y += v.y;
        q.x = fmaf(v.x, v.x, q.x);
        q.y = fmaf(v.y, v.y, q.y);
    }
    __shared__ float2 sh_s[8][32], sh_q[8][32];
    sh_s[warp][lane] = s;
    sh_q[warp][lane] = q;
    __syncthreads();
    if (warp == 0) {
        for (int i = 1; i < wpb; i++) {
            s.x += sh_s[i][lane].x; s.y += sh_s[i][lane].y;
            q.x += sh_q[i][lane].x; q.y += sh_q[i][lane].y;
        }
        atomicAdd(&sums[lane], s);
        atomicAdd(&sums[32 + lane], q);
    }
}

// fold BN into per-channel scale/shift (stored in packed-mem channel order)
__global__ void finalize_kernel(const float2* __restrict__ sums,
                                const float* __restrict__ gamma,
                                const float* __restrict__ beta,
                                float2* __restrict__ bnout, float invN) {
    int l = threadIdx.x;  // 0..31
    float2 s = sums[l], q = sums[32 + l];
    float mx = s.x * invN, my = s.y * invN;
    float vx = fmaf(q.x, invN, -mx * mx);
    float vy = fmaf(q.y, invN, -my * my);
    float scx = gamma[l] * rsqrtf(vx + 1e-5f);
    float scy = gamma[l + 32] * rsqrtf(vy + 1e-5f);
    bnout[l] = make_float2(scx, scy);
    bnout[32 + l] = make_float2(beta[l] - mx * scx, beta[l + 32] - my * scy);
}

// out = relu(bn2(y2) + x), packed scratch -> standard [N][64] output
__global__ __launch_bounds__(256) void final_kernel(const float2* __restrict__ y2,
                                                    const float* __restrict__ x,
                                                    const float2* __restrict__ bn,
                                                    float* __restrict__ out, int n32) {
    int i = blockIdx.x * blockDim.x + threadIdx.x;
    if (i >= n32) return;
    int l = i & 31, row = i >> 5;
    float2 v = y2[i];
    float2 sc = bn[l], sh = bn[32 + l];
    out[row * 64 + l]      = fmaxf(fmaf(v.x, sc.x, sh.x) + x[row * 64 + l], 0.f);
    out[row * 64 + l + 32] = fmaxf(fmaf(v.y, sc.y, sh.y) + x[row * 64 + l + 32], 0.f);
}

// ---------------------------------------------------------------------------
extern "C" void kernel_launch(void* const* d_in, const int* in_sizes, int n_in,
                              void* d_out, int out_size) {
    const float* x      = (const float*)d_in[0];
    // d_in[1] = norm_points (unused by reference math)
    const float* W1     = (const float*)d_in[2];
    const float* gamma1 = (const float*)d_in[3];
    const float* beta1  = (const float*)d_in[4];
    const float* W2     = (const float*)d_in[5];
    const float* gamma2 = (const float*)d_in[6];
    const float* beta2  = (const float*)d_in[7];
    const int* in_idx   = (const int*)d_in[8];
    const int* out_idx  = (const int*)d_in[9];

    const int N = in_sizes[0] / 64;          // 100000
    const int K = in_sizes[2] / (64 * 64);   // 27

    float2 *y1, *y2, *stats, *bn;
    cudaGetSymbolAddress((void**)&y1, g_y1);
    cudaGetSymbolAddress((void**)&y2, g_y2);
    cudaGetSymbolAddress((void**)&stats, g_stats);
    cudaGetSymbolAddress((void**)&bn, g_bn);

    cudaMemsetAsync(y1, 0, (size_t)N * 32 * sizeof(float2));
    cudaMemsetAsync(y2, 0, (size_t)N * 32 * sizeof(float2));
    cudaMemsetAsync(stats, 0, 4 * 32 * sizeof(float2));

    dim3 cgrid(40, K);
    const float invN = 1.0f / (float)N;

    // layer 1 (linear input)
    conv2_kernel<false, false><<<cgrid, 256>>>(x, W1, in_idx, out_idx, y1,
                                               nullptr, nullptr, N);
    stats_kernel<<<256, 256>>>(y1, stats, N);
    finalize_kernel<<<1, 32>>>(stats, gamma1, beta1, bn, invN);

    // layer 2 (packed input, BN1+ReLU folded into staging)
    conv2_kernel<true, true><<<cgrid, 256>>>((const float*)y1, W2, in_idx, out_idx, y2,
                                             (const float*)bn, (const float*)(bn + 32), N);
    stats_kernel<<<256, 256>>>(y2, stats + 64, N);
    finalize_kernel<<<1, 32>>>(stats + 64, gamma2, beta2, bn + 64, invN);

    // epilogue: BN2 + residual + ReLU
    final_kernel<<<(N * 32 + 255) / 256, 256>>>(y2, x, bn + 64, (float*)d_out, N * 32);
}

// round 4
// speedup vs baseline: 1.5546x; 1.0584x over previous
#include <cuda_runtime.h>
#include <cstdint>

// ============================================================================
// ResidualBlockWithPointsBase — mma.sync tf32 3-pass edition (sm_103-safe PTX)
//   y1 = conv(x, W1);  BN1 -> fold;  y2 = conv(relu(bn1(y1)), W2);  BN2 -> fold
//   out = relu(bn2(y2) + x)
// conv: persistent CTAs over (k, 128-edge tile):
//   gather rows -> smem (tf32 hi/lo, pad-68) -> warp mma.m16n8k8 (3xTF32),
//   W[k] hi/lo fragments register-resident, scatter via atomicAdd(float2).
// ============================================================================

#define MAXN 100352
typedef unsigned long long ull;

__device__ float g_y1[MAXN * 64];
__device__ float g_y2[MAXN * 64];
__device__ float2 g_stats[4 * 32];
__device__ float g_bn[4 * 64];

__device__ __forceinline__ float tf32_rna(float x) {
    float r;
    asm("cvt.rna.tf32.f32 %0, %1;" : "=f"(r) : "f"(x));
    return r;
}
__device__ __forceinline__ void mma_tf32(float* d, const uint32_t* a, const uint32_t* b) {
    asm volatile(
        "mma.sync.aligned.m16n8k8.row.col.f32.tf32.tf32.f32 "
        "{%0,%1,%2,%3}, {%4,%5,%6,%7}, {%8,%9}, {%0,%1,%2,%3};"
        : "+f"(d[0]), "+f"(d[1]), "+f"(d[2]), "+f"(d[3])
        : "r"(a[0]), "r"(a[1]), "r"(a[2]), "r"(a[3]), "r"(b[0]), "r"(b[1]));
}

// smem float offsets
#define A_PAD 68
#define OFF_AH 0
#define OFF_AL (128 * A_PAD)
#define OFF_SIDX (2 * 128 * A_PAD)
#define OFF_SOG (OFF_SIDX + 128)
#define OFF_BNS (OFF_SOG + 128)
#define OFF_BNH (OFF_BNS + 64)
#define SMEM_FLOATS (OFF_BNH + 64)
#define SMEM_BYTES (SMEM_FLOATS * 4)

// ---------------------------------------------------------------------------
template <bool BN>
__global__ __launch_bounds__(256, 1) void conv_mma_kernel(
    const float* __restrict__ xin,  // [N][64]
    const float* __restrict__ W,    // [K][64][64]
    const int* __restrict__ in_idx, const int* __restrict__ out_idx,
    float* __restrict__ yout,       // [N][64] pre-zeroed
    const float* __restrict__ bnscale, const float* __restrict__ bnshift,
    int nE, int K, int nblk) {
    extern __shared__ float sm[];
    float* Ah = sm + OFF_AH;
    float* Al = sm + OFF_AL;
    int* sidx = (int*)(sm + OFF_SIDX);
    int* sog = (int*)(sm + OFF_SOG);
    float* bns = sm + OFF_BNS;
    float* bnh = sm + OFF_BNH;

    const int tid = threadIdx.x;
    const int lane = tid & 31;
    const int wid = tid >> 5;
    const int gi = lane >> 2;  // group id 0..7
    const int tq = lane & 3;   // quad thread 0..3
    const int EB = (wid >> 1) * 32;     // warp's edge base (32 edges)
    const int NBASE = (wid & 1) * 32;   // warp's cout base (32 couts)

    if (BN) {
        if (tid < 64) bns[tid] = bnscale[tid];
        else if (tid < 128) bnh[tid - 64] = bnshift[tid - 64];
    }
    __syncthreads();

    const int tilesPerK = (nE + 127) >> 7;
    const int total = K * tilesPerK;
    const int chunk = (total + nblk - 1) / nblk;
    const int it0 = blockIdx.x * chunk;
    const int it1 = min(it0 + chunk, total);

    // W[k] fragments, register-resident: [n-tile][k-chunk][reg], hi & lo
    uint32_t Bh[4][8][2], Bl[4][8][2];
    int cur_k = -1;

    for (int item = it0; item < it1; item++) {
        const int k = item / tilesPerK;
        const int tile = item - k * tilesPerK;

        if (k != cur_k) {
            cur_k = k;
            const float* Wk = W + (size_t)k * 4096;
#pragma unroll
            for (int kc = 0; kc < 8; kc++)
#pragma unroll
                for (int nt = 0; nt < 4; nt++)
#pragma unroll
                    for (int r = 0; r < 2; r++) {
                        // B frag (col): row = cin = kc*8 + tq + 4r, col = cout
                        float w = __ldg(Wk + (size_t)(kc * 8 + tq + 4 * r) * 64 +
                                        NBASE + nt * 8 + gi);
                        float h = tf32_rna(w);
                        Bh[nt][kc][r] = __float_as_uint(h);
                        Bl[nt][kc][r] = __float_as_uint(tf32_rna(w - h));
                    }
        }

        __syncthreads();  // WAR: prev tile's A/sog reads complete

        if (tid < 128) {
            int e = tile * 128 + tid;
            bool v = e < nE;
            sidx[tid] = v ? __ldg(in_idx + (size_t)k * nE + e) : 0;
            sog[tid] = v ? __ldg(out_idx + (size_t)k * nE + e) : -1;
        }
        __syncthreads();

        // ---- gather 128 rows -> Ah/Al (2 threads per row, interleaved chunks) ----
        {
            const int row = tid >> 1, h = tid & 1;
            const float4* src = (const float4*)(xin + (size_t)sidx[row] * 64);
#pragma unroll
            for (int j = 0; j < 8; j++) {
                const int c4 = 2 * j + h;  // float4 chunk 0..15
                float4 v = __ldg(src + c4);
                if (BN) {
                    float4 s4 = *(const float4*)(bns + c4 * 4);
                    float4 h4 = *(const float4*)(bnh + c4 * 4);
                    v.x = fmaxf(fmaf(v.x, s4.x, h4.x), 0.f);
                    v.y = fmaxf(fmaf(v.y, s4.y, h4.y), 0.f);
                    v.z = fmaxf(fmaf(v.z, s4.z, h4.z), 0.f);
                    v.w = fmaxf(fmaf(v.w, s4.w, h4.w), 0.f);
                }
                float4 hi, lo;
                hi.x = tf32_rna(v.x); lo.x = tf32_rna(v.x - hi.x);
                hi.y = tf32_rna(v.y); lo.y = tf32_rna(v.y - hi.y);
                hi.z = tf32_rna(v.z); lo.z = tf32_rna(v.z - hi.z);
                hi.w = tf32_rna(v.w); lo.w = tf32_rna(v.w - hi.w);
                *(float4*)(Ah + row * A_PAD + c4 * 4) = hi;
                *(float4*)(Al + row * A_PAD + c4 * 4) = lo;
            }
        }
        __syncthreads();

        // ---- compute: 2 m-tiles x 4 n-tiles, K = 8 chunks, 3 passes ----
        float acc[2][4][4];
#pragma unroll
        for (int mt = 0; mt < 2; mt++)
#pragma unroll
            for (int nt = 0; nt < 4; nt++)
#pragma unroll
                for (int r = 0; r < 4; r++) acc[mt][nt][r] = 0.f;

#pragma unroll
        for (int kc = 0; kc < 8; kc++) {
            uint32_t ah[2][4], al[2][4];
#pragma unroll
            for (int mt = 0; mt < 2; mt++) {
                const float* p = Ah + (EB + mt * 16 + gi) * A_PAD + kc * 8 + tq;
                ah[mt][0] = __float_as_uint(p[0]);
                ah[mt][1] = __float_as_uint(p[8 * A_PAD]);
                ah[mt][2] = __float_as_uint(p[4]);
                ah[mt][3] = __float_as_uint(p[8 * A_PAD + 4]);
                const float* q = Al + (EB + mt * 16 + gi) * A_PAD + kc * 8 + tq;
                al[mt][0] = __float_as_uint(q[0]);
                al[mt][1] = __float_as_uint(q[8 * A_PAD]);
                al[mt][2] = __float_as_uint(q[4]);
                al[mt][3] = __float_as_uint(q[8 * A_PAD + 4]);
            }
#pragma unroll
            for (int mt = 0; mt < 2; mt++)
#pragma unroll
                for (int nt = 0; nt < 4; nt++) {
                    mma_tf32(acc[mt][nt], ah[mt], Bh[nt][kc]);
                    mma_tf32(acc[mt][nt], al[mt], Bh[nt][kc]);
                    mma_tf32(acc[mt][nt], ah[mt], Bl[nt][kc]);
                }
        }

        // ---- scatter: D[m=edge][n=cout]; c0/c1 = adjacent couts ----
#pragma unroll
        for (int mt = 0; mt < 2; mt++) {
            const int r0 = EB + mt * 16 + gi;
            const int og0 = sog[r0];
            const int og1 = sog[r0 + 8];
#pragma unroll
            for (int nt = 0; nt < 4; nt++) {
                const int cout = NBASE + nt * 8 + 2 * tq;
                if (og0 >= 0)
                    atomicAdd((float2*)(yout + (size_t)og0 * 64 + cout),
                              make_float2(acc[mt][nt][0], acc[mt][nt][1]));
                if (og1 >= 0)
                    atomicAdd((float2*)(yout + (size_t)og1 * 64 + cout),
                              make_float2(acc[mt][nt][2], acc[mt][nt][3]));
            }
        }
    }
}

// ---------------------------------------------------------------------------
__global__ __launch_bounds__(256) void stats_kernel(const float* __restrict__ y,
                                                    float2* __restrict__ sums, int n) {
    const int lane = threadIdx.x & 31;
    const int warp = threadIdx.x >> 5;
    const int wpb = blockDim.x >> 5;

    float2 s = {0.f, 0.f}, q = {0.f, 0.f};
    for (int r = blockIdx.x * wpb + warp; r < n; r += gridDim.x * wpb) {
        float2 v = *(const float2*)(y + (size_t)r * 64 + 2 * lane);
        s.x += v.x; s.y += v.y;
        q.x = fmaf(v.x, v.x, q.x);
        q.y = fmaf(v.y, v.y, q.y);
    }
    __shared__ float2 sh_s[8][32], sh_q[8][32];
    sh_s[warp][lane] = s;
    sh_q[warp][lane] = q;
    __syncthreads();
    if (warp == 0) {
        for (int i = 1; i < wpb; i++) {
            s.x += sh_s[i][lane].x; s.y += sh_s[i][lane].y;
            q.x += sh_q[i][lane].x; q.y += sh_q[i][lane].y;
        }
        atomicAdd(&sums[lane], s);
        atomicAdd(&sums[32 + lane], q);
    }
}

__global__ void finalize_kernel(const float2* __restrict__ sums,
                                const float* __restrict__ gamma,
                                const float* __restrict__ beta,
                                float* __restrict__ bnout, float invN) {
    int l = threadIdx.x;  // 0..31 -> channels 2l, 2l+1
    float2 s = sums[l], q = sums[32 + l];
    float m0 = s.x * invN, m1 = s.y * invN;
    float v0 = fmaf(q.x, invN, -m0 * m0);
    float v1 = fmaf(q.y, invN, -m1 * m1);
    float sc0 = gamma[2 * l] * rsqrtf(v0 + 1e-5f);
    float sc1 = gamma[2 * l + 1] * rsqrtf(v1 + 1e-5f);
    bnout[2 * l] = sc0;
    bnout[2 * l + 1] = sc1;
    bnout[64 + 2 * l] = beta[2 * l] - m0 * sc0;
    bnout[64 + 2 * l + 1] = beta[2 * l + 1] - m1 * sc1;
}

__global__ __launch_bounds__(256) void final_kernel(const float4* __restrict__ y2,
                                                    const float4* __restrict__ x,
                                                    const float* __restrict__ bn,
                                                    float4* __restrict__ out, int n4) {
    int i = blockIdx.x * blockDim.x + threadIdx.x;
    if (i >= n4) return;
    int c4 = (i & 15) * 4;
    float4 v = y2[i], xr = x[i];
    float4 sc = *(const float4*)(bn + c4);
    float4 sh = *(const float4*)(bn + 64 + c4);
    float4 o;
    o.x = fmaxf(fmaf(v.x, sc.x, sh.x) + xr.x, 0.f);
    o.y = fmaxf(fmaf(v.y, sc.y, sh.y) + xr.y, 0.f);
    o.z = fmaxf(fmaf(v.z, sc.z, sh.z) + xr.z, 0.f);
    o.w = fmaxf(fmaf(v.w, sc.w, sh.w) + xr.w, 0.f);
    out[i] = o;
}

// ---------------------------------------------------------------------------
extern "C" void kernel_launch(void* const* d_in, const int* in_sizes, int n_in,
                              void* d_out, int out_size) {
    const float* x      = (const float*)d_in[0];
    const float* W1     = (const float*)d_in[2];
    const float* gamma1 = (const float*)d_in[3];
    const float* beta1  = (const float*)d_in[4];
    const float* W2     = (const float*)d_in[5];
    const float* gamma2 = (const float*)d_in[6];
    const float* beta2  = (const float*)d_in[7];
    const int* in_idx   = (const int*)d_in[8];
    const int* out_idx  = (const int*)d_in[9];

    const int N = in_sizes[0] / 64;
    const int K = in_sizes[2] / (64 * 64);

    float *y1, *y2, *bn;
    float2* stats;
    cudaGetSymbolAddress((void**)&y1, g_y1);
    cudaGetSymbolAddress((void**)&y2, g_y2);
    cudaGetSymbolAddress((void**)&stats, g_stats);
    cudaGetSymbolAddress((void**)&bn, g_bn);

    cudaFuncSetAttribute(conv_mma_kernel<false>,
                         cudaFuncAttributeMaxDynamicSharedMemorySize, SMEM_BYTES);
    cudaFuncSetAttribute(conv_mma_kernel<true>,
                         cudaFuncAttributeMaxDynamicSharedMemorySize, SMEM_BYTES);

    cudaMemsetAsync(y1, 0, (size_t)N * 64 * sizeof(float));
    cudaMemsetAsync(y2, 0, (size_t)N * 64 * sizeof(float));
    cudaMemsetAsync(stats, 0, 4 * 32 * sizeof(float2));

    const int NB = 148;
    const float invN = 1.0f / (float)N;

    conv_mma_kernel<false><<<NB, 256, SMEM_BYTES>>>(x, W1, in_idx, out_idx, y1,
                                                    nullptr, nullptr, N, K, NB);
    stats_kernel<<<256, 256>>>(y1, stats, N);
    finalize_kernel<<<1, 32>>>(stats, gamma1, beta1, bn, invN);

    conv_mma_kernel<true><<<NB, 256, SMEM_BYTES>>>(y1, W2, in_idx, out_idx, y2,
                                                   bn, bn + 64, N, K, NB);
    stats_kernel<<<256, 256>>>(y2, stats + 64, N);
    finalize_kernel<<<1, 32>>>(stats + 64, gamma2, beta2, bn + 128, invN);

    final_kernel<<<(N * 16 + 255) / 256, 256>>>((const float4*)y2, (const float4*)x,
                                                bn + 128, (float4*)d_out, N * 16);
}

// round 5
// speedup vs baseline: 1.8797x; 1.2091x over previous
#include <cuda_runtime.h>
#include <cstdint>

// ============================================================================
// ResidualBlockWithPointsBase — mma.sync tf32 3-pass, occupancy-2 edition
//   y1 = conv(x, W1);  BN1 -> fold;  y2 = conv(relu(bn1(y1)), W2);  BN2 -> fold
//   out = relu(bn2(y2) + x)
// conv: persistent CTAs over (k, 128-edge tile):
//   gather rows -> smem (tf32 hi/lo, pad-68) -> warp mma.m16n8k8 (3xTF32),
//   W[k] hi/lo in SMEM transposed (pad-68), scatter via atomicAdd(float2).
//   2 CTAs/SM so one CTA's MMA covers the other's gather latency.
// ============================================================================

#define MAXN 100352
typedef unsigned long long ull;

__device__ float g_y1[MAXN * 64];
__device__ float g_y2[MAXN * 64];
__device__ float2 g_stats[4 * 32];
__device__ float g_bn[4 * 64];

__device__ __forceinline__ float tf32_rna(float x) {
    float r;
    asm("cvt.rna.tf32.f32 %0, %1;" : "=f"(r) : "f"(x));
    return r;
}
__device__ __forceinline__ void mma_tf32(float* d, const uint32_t* a, const uint32_t* b) {
    asm volatile(
        "mma.sync.aligned.m16n8k8.row.col.f32.tf32.tf32.f32 "
        "{%0,%1,%2,%3}, {%4,%5,%6,%7}, {%8,%9}, {%0,%1,%2,%3};"
        : "+f"(d[0]), "+f"(d[1]), "+f"(d[2]), "+f"(d[3])
        : "r"(a[0]), "r"(a[1]), "r"(a[2]), "r"(a[3]), "r"(b[0]), "r"(b[1]));
}

// smem float offsets
#define A_PAD 68
#define W_PAD 68
#define OFF_AH 0
#define OFF_AL (128 * A_PAD)                  // 8704
#define OFF_WH (2 * 128 * A_PAD)              // 17408
#define OFF_WL (OFF_WH + 64 * W_PAD)          // +4352
#define OFF_BNS (OFF_WL + 64 * W_PAD)
#define OFF_BNH (OFF_BNS + 64)
#define SMEM_FLOATS (OFF_BNH + 64)
#define SMEM_BYTES (SMEM_FLOATS * 4)          // ~104.4 KB

// ---------------------------------------------------------------------------
template <bool BN>
__global__ __launch_bounds__(256, 2) void conv_mma_kernel(
    const float* __restrict__ xin,  // [N][64]
    const float* __restrict__ W,    // [K][64][64]
    const int* __restrict__ in_idx, const int* __restrict__ out_idx,
    float* __restrict__ yout,       // [N][64] pre-zeroed
    const float* __restrict__ bnscale, const float* __restrict__ bnshift,
    int nE, int K, int nblk) {
    extern __shared__ float sm[];
    float* Ah = sm + OFF_AH;
    float* Al = sm + OFF_AL;
    float* Wh = sm + OFF_WH;   // transposed: Wh[col*W_PAD + row]
    float* Wl = sm + OFF_WL;
    float* bns = sm + OFF_BNS;
    float* bnh = sm + OFF_BNH;

    const int tid = threadIdx.x;
    const int lane = tid & 31;
    const int wid = tid >> 5;
    const int gi = lane >> 2;  // group id 0..7
    const int tq = lane & 3;   // quad thread 0..3
    const int EB = (wid >> 1) * 32;    // warp's edge base (32 edges)
    const int NBASE = (wid & 1) * 32;  // warp's cout base (32 couts)

    if (BN) {
        if (tid < 64) bns[tid] = bnscale[tid];
        else if (tid < 128) bnh[tid - 64] = bnshift[tid - 64];
    }

    const int tilesPerK = (nE + 127) >> 7;
    const int total = K * tilesPerK;
    const int chunk = (total + nblk - 1) / nblk;
    const int it0 = blockIdx.x * chunk;
    const int it1 = min(it0 + chunk, total);

    int cur_k = -1;

    for (int item = it0; item < it1; item++) {
        const int k = item / tilesPerK;
        const int tile = item - k * tilesPerK;
        const int ebase = tile * 128;

        if (k != cur_k) {
            cur_k = k;
            __syncthreads();  // WAR on W (and A) from previous tile
            const float* Wk = W + (size_t)k * 4096;
            for (int i = tid; i < 4096; i += 256) {
                int row = i >> 6, col = i & 63;
                float w = __ldg(Wk + i);
                float h = tf32_rna(w);
                Wh[col * W_PAD + row] = h;
                Wl[col * W_PAD + row] = tf32_rna(w - h);
            }
        }

        __syncthreads();  // WAR: prev tile's A reads complete / W staged

        // ---- gather 128 rows -> Ah/Al (2 threads per row, interleaved chunks) ----
        {
            const int row = tid >> 1, h = tid & 1;
            const int e = ebase + row;
            const int src_row = (e < nE) ? __ldg(in_idx + (size_t)k * nE + e) : 0;
            const float4* src = (const float4*)(xin + (size_t)src_row * 64);
#pragma unroll
            for (int j = 0; j < 8; j++) {
                const int c4 = 2 * j + h;  // float4 chunk 0..15
                float4 v = __ldg(src + c4);
                if (BN) {
                    float4 s4 = *(const float4*)(bns + c4 * 4);
                    float4 h4 = *(const float4*)(bnh + c4 * 4);
                    v.x = fmaxf(fmaf(v.x, s4.x, h4.x), 0.f);
                    v.y = fmaxf(fmaf(v.y, s4.y, h4.y), 0.f);
                    v.z = fmaxf(fmaf(v.z, s4.z, h4.z), 0.f);
                    v.w = fmaxf(fmaf(v.w, s4.w, h4.w), 0.f);
                }
                float4 hi, lo;
                hi.x = tf32_rna(v.x); lo.x = tf32_rna(v.x - hi.x);
                hi.y = tf32_rna(v.y); lo.y = tf32_rna(v.y - hi.y);
                hi.z = tf32_rna(v.z); lo.z = tf32_rna(v.z - hi.z);
                hi.w = tf32_rna(v.w); lo.w = tf32_rna(v.w - hi.w);
                *(float4*)(Ah + row * A_PAD + c4 * 4) = hi;
                *(float4*)(Al + row * A_PAD + c4 * 4) = lo;
            }
        }
        __syncthreads();

        // ---- compute: 2 m-tiles x 4 n-tiles, K = 8 chunks, 3 passes ----
        float acc[2][4][4];
#pragma unroll
        for (int mt = 0; mt < 2; mt++)
#pragma unroll
            for (int nt = 0; nt < 4; nt++)
#pragma unroll
                for (int r = 0; r < 4; r++) acc[mt][nt][r] = 0.f;

#pragma unroll
        for (int kc = 0; kc < 8; kc++) {
            // A fragments
            uint32_t ah[2][4], al[2][4];
#pragma unroll
            for (int mt = 0; mt < 2; mt++) {
                const float* p = Ah + (EB + mt * 16 + gi) * A_PAD + kc * 8 + tq;
                ah[mt][0] = __float_as_uint(p[0]);
                ah[mt][1] = __float_as_uint(p[8 * A_PAD]);
                ah[mt][2] = __float_as_uint(p[4]);
                ah[mt][3] = __float_as_uint(p[8 * A_PAD + 4]);
                const float* q = Al + (EB + mt * 16 + gi) * A_PAD + kc * 8 + tq;
                al[mt][0] = __float_as_uint(q[0]);
                al[mt][1] = __float_as_uint(q[8 * A_PAD]);
                al[mt][2] = __float_as_uint(q[4]);
                al[mt][3] = __float_as_uint(q[8 * A_PAD + 4]);
            }
            // B fragments from transposed W smem: row = kc*8+tq(+4), col per nt
#pragma unroll
            for (int nt = 0; nt < 4; nt++) {
                const int col = NBASE + nt * 8 + gi;
                const float* wp = Wh + col * W_PAD + kc * 8 + tq;
                const float* wq = Wl + col * W_PAD + kc * 8 + tq;
                uint32_t bh[2], bl[2];
                bh[0] = __float_as_uint(wp[0]);
                bh[1] = __float_as_uint(wp[4]);
                bl[0] = __float_as_uint(wq[0]);
                bl[1] = __float_as_uint(wq[4]);
#pragma unroll
                for (int mt = 0; mt < 2; mt++) {
                    mma_tf32(acc[mt][nt], ah[mt], bh);
                    mma_tf32(acc[mt][nt], al[mt], bh);
                    mma_tf32(acc[mt][nt], ah[mt], bl);
                }
            }
        }

        // ---- scatter: D[m=edge][n=cout] ----
        const int* oi = out_idx + (size_t)k * nE + ebase;
#pragma unroll
        for (int mt = 0; mt < 2; mt++) {
            const int r0 = EB + mt * 16 + gi;
            const int og0 = (ebase + r0 < nE) ? __ldg(oi + r0) : -1;
            const int og1 = (ebase + r0 + 8 < nE) ? __ldg(oi + r0 + 8) : -1;
#pragma unroll
            for (int nt = 0; nt < 4; nt++) {
                const int cout = NBASE + nt * 8 + 2 * tq;
                if (og0 >= 0)
                    atomicAdd((float2*)(yout + (size_t)og0 * 64 + cout),
                              make_float2(acc[mt][nt][0], acc[mt][nt][1]));
                if (og1 >= 0)
                    atomicAdd((float2*)(yout + (size_t)og1 * 64 + cout),
                              make_float2(acc[mt][nt][2], acc[mt][nt][3]));
            }
        }
    }
}

// ---------------------------------------------------------------------------
__global__ __launch_bounds__(256) void stats_kernel(const float* __restrict__ y,
                                                    float2* __restrict__ sums, int n) {
    const int lane = threadIdx.x & 31;
    const int warp = threadIdx.x >> 5;
    const int wpb = blockDim.x >> 5;

    float2 s = {0.f, 0.f}, q = {0.f, 0.f};
    for (int r = blockIdx.x * wpb + warp; r < n; r += gridDim.x * wpb) {
        float2 v = *(const float2*)(y + (size_t)r * 64 + 2 * lane);
        s.x += v.x; s.y += v.y;
        q.x = fmaf(v.x, v.x, q.x);
        q.y = fmaf(v.y, v.y, q.y);
    }
    __shared__ float2 sh_s[8][32], sh_q[8][32];
    sh_s[warp][lane] = s;
    sh_q[warp][lane] = q;
    __syncthreads();
    if (warp == 0) {
        for (int i = 1; i < wpb; i++) {
            s.x += sh_s[i][lane].x; s.y += sh_s[i][lane].y;
            q.x += sh_q[i][lane].x; q.y += sh_q[i][lane].y;
        }
        atomicAdd(&sums[lane], s);
        atomicAdd(&sums[32 + lane], q);
    }
}

__global__ void finalize_kernel(const float2* __restrict__ sums,
                                const float* __restrict__ gamma,
                                const float* __restrict__ beta,
                                float* __restrict__ bnout, float invN) {
    int l = threadIdx.x;  // 0..31 -> channels 2l, 2l+1
    float2 s = sums[l], q = sums[32 + l];
    float m0 = s.x * invN, m1 = s.y * invN;
    float v0 = fmaf(q.x, invN, -m0 * m0);
    float v1 = fmaf(q.y, invN, -m1 * m1);
    float sc0 = gamma[2 * l] * rsqrtf(v0 + 1e-5f);
    float sc1 = gamma[2 * l + 1] * rsqrtf(v1 + 1e-5f);
    bnout[2 * l] = sc0;
    bnout[2 * l + 1] = sc1;
    bnout[64 + 2 * l] = beta[2 * l] - m0 * sc0;
    bnout[64 + 2 * l + 1] = beta[2 * l + 1] - m1 * sc1;
}

__global__ __launch_bounds__(256) void final_kernel(const float4* __restrict__ y2,
                                                    const float4* __restrict__ x,
                                                    const float* __restrict__ bn,
                                                    float4* __restrict__ out, int n4) {
    int i = blockIdx.x * blockDim.x + threadIdx.x;
    if (i >= n4) return;
    int c4 = (i & 15) * 4;
    float4 v = y2[i], xr = x[i];
    float4 sc = *(const float4*)(bn + c4);
    float4 sh = *(const float4*)(bn + 64 + c4);
    float4 o;
    o.x = fmaxf(fmaf(v.x, sc.x, sh.x) + xr.x, 0.f);
    o.y = fmaxf(fmaf(v.y, sc.y, sh.y) + xr.y, 0.f);
    o.z = fmaxf(fmaf(v.z, sc.z, sh.z) + xr.z, 0.f);
    o.w = fmaxf(fmaf(v.w, sc.w, sh.w) + xr.w, 0.f);
    out[i] = o;
}

// ---------------------------------------------------------------------------
extern "C" void kernel_launch(void* const* d_in, const int* in_sizes, int n_in,
                              void* d_out, int out_size) {
    const float* x      = (const float*)d_in[0];
    const float* W1     = (const float*)d_in[2];
    const float* gamma1 = (const float*)d_in[3];
    const float* beta1  = (const float*)d_in[4];
    const float* W2     = (const float*)d_in[5];
    const float* gamma2 = (const float*)d_in[6];
    const float* beta2  = (const float*)d_in[7];
    const int* in_idx   = (const int*)d_in[8];
    const int* out_idx  = (const int*)d_in[9];

    const int N = in_sizes[0] / 64;
    const int K = in_sizes[2] / (64 * 64);

    float *y1, *y2, *bn;
    float2* stats;
    cudaGetSymbolAddress((void**)&y1, g_y1);
    cudaGetSymbolAddress((void**)&y2, g_y2);
    cudaGetSymbolAddress((void**)&stats, g_stats);
    cudaGetSymbolAddress((void**)&bn, g_bn);

    cudaFuncSetAttribute(conv_mma_kernel<false>,
                         cudaFuncAttributeMaxDynamicSharedMemorySize, SMEM_BYTES);
    cudaFuncSetAttribute(conv_mma_kernel<true>,
                         cudaFuncAttributeMaxDynamicSharedMemorySize, SMEM_BYTES);

    cudaMemsetAsync(y1, 0, (size_t)N * 64 * sizeof(float));
    cudaMemsetAsync(y2, 0, (size_t)N * 64 * sizeof(float));
    cudaMemsetAsync(stats, 0, 4 * 32 * sizeof(float2));

    const int NB = 296;  // 2 CTAs per SM
    const float invN = 1.0f / (float)N;

    conv_mma_kernel<false><<<NB, 256, SMEM_BYTES>>>(x, W1, in_idx, out_idx, y1,
                                                    nullptr, nullptr, N, K, NB);
    stats_kernel<<<256, 256>>>(y1, stats, N);
    finalize_kernel<<<1, 32>>>(stats, gamma1, beta1, bn, invN);

    conv_mma_kernel<true><<<NB, 256, SMEM_BYTES>>>(y1, W2, in_idx, out_idx, y2,
                                                   bn, bn + 64, N, K, NB);
    stats_kernel<<<256, 256>>>(y2, stats + 64, N);
    finalize_kernel<<<1, 32>>>(stats + 64, gamma2, beta2, bn + 128, invN);

    final_kernel<<<(N * 16 + 255) / 256, 256>>>((const float4*)y2, (const float4*)x,
                                                bn + 128, (float4*)d_out, N * 16);
}

// round 6
// speedup vs baseline: 2.0681x; 1.1002x over previous
#include <cuda_runtime.h>
#include <cstdint>

// ============================================================================
// ResidualBlockWithPointsBase — mma.sync tf32 3-pass + cp.async pipeline
//   y1 = conv(x, W1); BN1 fold; y1a = relu(bn1(y1));
//   y2 = conv(y1a, W2); BN2 fold; out = relu(bn2(y2) + x)
// conv: persistent CTAs over (k, 128-edge tile):
//   cp.async double-buffered gather (raw fp32) -> in-register tf32 hi/lo ->
//   warp mma.m16n8k8 (3xTF32, W in smem pad-68, column-permuted) ->
//   red.global.add.v4.f32 scatter. 2 CTAs/SM.
// ============================================================================

#define MAXN 100352
typedef unsigned long long ull;

__device__ float g_y1[MAXN * 64];
__device__ float g_y1a[MAXN * 64];
__device__ float g_y2[MAXN * 64];
__device__ float2 g_stats[4 * 32];
__device__ float g_bn[4 * 64];

__device__ __forceinline__ float tf32_rna(float x) {
    float r;
    asm("cvt.rna.tf32.f32 %0, %1;" : "=f"(r) : "f"(x));
    return r;
}
__device__ __forceinline__ void mma_tf32(float* d, const uint32_t* a, const uint32_t* b) {
    asm volatile(
        "mma.sync.aligned.m16n8k8.row.col.f32.tf32.tf32.f32 "
        "{%0,%1,%2,%3}, {%4,%5,%6,%7}, {%8,%9}, {%0,%1,%2,%3};"
        : "+f"(d[0]), "+f"(d[1]), "+f"(d[2]), "+f"(d[3])
        : "r"(a[0]), "r"(a[1]), "r"(a[2]), "r"(a[3]), "r"(b[0]), "r"(b[1]));
}
__device__ __forceinline__ void red_add_v4(float* g, float a, float b, float c, float d) {
    asm volatile("red.global.add.v4.f32 [%0], {%1, %2, %3, %4};"
                 :: "l"(g), "f"(a), "f"(b), "f"(c), "f"(d) : "memory");
}
#define CP_ASYNC16(dst, src) \
    asm volatile("cp.async.ca.shared.global [%0], [%1], 16;" :: "r"(dst), "l"(src))
#define CP_COMMIT() asm volatile("cp.async.commit_group;" ::: "memory")
#define CP_WAIT1() asm volatile("cp.async.wait_group 1;" ::: "memory")
#define CP_WAIT0() asm volatile("cp.async.wait_group 0;" ::: "memory")

// smem float offsets
#define A_PAD 68
#define W_PAD 68
#define OFF_A0 0
#define OFF_A1 (128 * A_PAD)
#define OFF_WH (2 * 128 * A_PAD)
#define OFF_WL (OFF_WH + 64 * W_PAD)
#define SMEM_FLOATS (OFF_WL + 64 * W_PAD)
#define SMEM_BYTES (SMEM_FLOATS * 4)  // 104448

// ---------------------------------------------------------------------------
__global__ __launch_bounds__(256, 2) void conv_mma_kernel(
    const float* __restrict__ xin,  // [N][64]
    const float* __restrict__ W,    // [K][64][64]
    const int* __restrict__ in_idx, const int* __restrict__ out_idx,
    float* __restrict__ yout,       // [N][64] pre-zeroed
    int nE, int K, int nblk) {
    extern __shared__ float sm[];
    float* Wh = sm + OFF_WH;  // transposed, col-permuted: Wh[colP*W_PAD + row]
    float* Wl = sm + OFF_WL;

    const int tid = threadIdx.x;
    const int lane = tid & 31;
    const int wid = tid >> 5;
    const int gi = lane >> 2;
    const int tq = lane & 3;
    const int EB = (wid >> 1) * 32;    // warp's edge base
    const int NBASE = (wid & 1) * 32;  // warp's cout base

    const int tilesPerK = (nE + 127) >> 7;
    const int total = K * tilesPerK;
    const int chunk = (total + nblk - 1) / nblk;
    const int it0 = blockIdx.x * chunk;
    const int it1 = min(it0 + chunk, total);
    if (it0 >= it1) return;

    // gather assignment: thread covers row = tid>>1, chunks c4 = 2j + (tid&1)
    const int grow = tid >> 1;
    const int ghalf = tid & 1;

    // load in_idx for a tile item (this thread's row), guarded
    auto load_idx = [&](int item) -> int {
        int k = item / tilesPerK;
        int e = (item - k * tilesPerK) * 128 + grow;
        return (e < nE) ? __ldg(in_idx + (size_t)k * nE + e) : 0;
    };
    // issue cp.async for tile item into buffer (item&1), given this thread's src row
    auto issue = [&](int item, int src_row) {
        const float* src = xin + (size_t)src_row * 64 + 4 * ghalf;
        float* dstf = sm + ((item & 1) ? OFF_A1 : OFF_A0) + grow * A_PAD + 4 * ghalf;
        uint32_t d = (uint32_t)__cvta_generic_to_shared(dstf);
#pragma unroll
        for (int j = 0; j < 8; j++) CP_ASYNC16(d + j * 32, src + 8 * j);
        CP_COMMIT();
    };

    int cur_k = -1;

    // prologue: prefetch tile it0; preload idx for it0+1
    int nidx = load_idx(it0);
    issue(it0, nidx);
    nidx = (it0 + 1 < it1) ? load_idx(it0 + 1) : 0;

    for (int item = it0; item < it1; item++) {
        const int k = item / tilesPerK;
        const int tile = item - k * tilesPerK;
        const int ebase = tile * 128;

        if (item + 1 < it1) {
            issue(item + 1, nidx);
            nidx = (item + 2 < it1) ? load_idx(item + 2) : 0;
            CP_WAIT1();
        } else {
            CP_WAIT0();
        }
        __syncthreads();  // tile `item` data visible to all

        if (k != cur_k) {  // W restage (old readers done: sync at end of prev iter)
            cur_k = k;
            const float* Wk = W + (size_t)k * 4096;
            for (int i = tid; i < 4096; i += 256) {
                int row = i >> 6, colP = i & 63;
                int l16 = colP & 15;
                // inverse column permutation (for v4 scatter):
                int Lcol = (colP & ~15) + 4 * ((l16 >> 1) & 3) + 2 * ((l16 >> 3) & 1) + (l16 & 1);
                float w = __ldg(Wk + (size_t)row * 64 + Lcol);
                float hh = tf32_rna(w);
                Wh[colP * W_PAD + row] = hh;
                Wl[colP * W_PAD + row] = tf32_rna(w - hh);
            }
            __syncthreads();
        }

        const float* Abuf = sm + ((item & 1) ? OFF_A1 : OFF_A0);

        // ---- compute: 2 m-tiles x 4 n-tiles, 8 k-chunks, 3 passes ----
        float acc[2][4][4];
#pragma unroll
        for (int mt = 0; mt < 2; mt++)
#pragma unroll
            for (int nt = 0; nt < 4; nt++)
#pragma unroll
                for (int r = 0; r < 4; r++) acc[mt][nt][r] = 0.f;

#pragma unroll
        for (int kc = 0; kc < 8; kc++) {
            uint32_t ah[2][4], al[2][4];
#pragma unroll
            for (int mt = 0; mt < 2; mt++) {
                const float* p = Abuf + (EB + mt * 16 + gi) * A_PAD + kc * 8 + tq;
                float r0 = p[0], r1 = p[8 * A_PAD], r2 = p[4], r3 = p[8 * A_PAD + 4];
                float h0 = tf32_rna(r0), h1 = tf32_rna(r1);
                float h2 = tf32_rna(r2), h3 = tf32_rna(r3);
                ah[mt][0] = __float_as_uint(h0);
                ah[mt][1] = __float_as_uint(h1);
                ah[mt][2] = __float_as_uint(h2);
                ah[mt][3] = __float_as_uint(h3);
                al[mt][0] = __float_as_uint(tf32_rna(r0 - h0));
                al[mt][1] = __float_as_uint(tf32_rna(r1 - h1));
                al[mt][2] = __float_as_uint(tf32_rna(r2 - h2));
                al[mt][3] = __float_as_uint(tf32_rna(r3 - h3));
            }
#pragma unroll
            for (int nt = 0; nt < 4; nt++) {
                const int col = NBASE + nt * 8 + gi;
                const float* wp = Wh + col * W_PAD + kc * 8 + tq;
                const float* wq = Wl + col * W_PAD + kc * 8 + tq;
                uint32_t bh[2], bl[2];
                bh[0] = __float_as_uint(wp[0]);
                bh[1] = __float_as_uint(wp[4]);
                bl[0] = __float_as_uint(wq[0]);
                bl[1] = __float_as_uint(wq[4]);
#pragma unroll
                for (int mt = 0; mt < 2; mt++) {
                    mma_tf32(acc[mt][nt], ah[mt], bh);
                    mma_tf32(acc[mt][nt], al[mt], bh);
                    mma_tf32(acc[mt][nt], ah[mt], bl);
                }
            }
        }

        // ---- scatter: thread owns logical couts NBASE+16p+4tq..+3 (v4) ----
        const int* oi = out_idx + (size_t)k * nE + ebase;
#pragma unroll
        for (int mt = 0; mt < 2; mt++) {
            const int r0 = EB + mt * 16 + gi;
            const int og0 = (ebase + r0 < nE) ? __ldg(oi + r0) : -1;
            const int og1 = (ebase + r0 + 8 < nE) ? __ldg(oi + r0 + 8) : -1;
#pragma unroll
            for (int p = 0; p < 2; p++) {
                const int cbase = NBASE + 16 * p + 4 * tq;
                if (og0 >= 0)
                    red_add_v4(yout + (size_t)og0 * 64 + cbase,
                               acc[mt][2 * p][0], acc[mt][2 * p][1],
                               acc[mt][2 * p + 1][0], acc[mt][2 * p + 1][1]);
                if (og1 >= 0)
                    red_add_v4(yout + (size_t)og1 * 64 + cbase,
                               acc[mt][2 * p][2], acc[mt][2 * p][3],
                               acc[mt][2 * p + 1][2], acc[mt][2 * p + 1][3]);
            }
        }
        __syncthreads();  // all reads of buffer (item&1) done -> reusable
    }
}

// ---------------------------------------------------------------------------
__global__ __launch_bounds__(256) void stats_kernel(const float* __restrict__ y,
                                                    float2* __restrict__ sums, int n) {
    const int lane = threadIdx.x & 31;
    const int warp = threadIdx.x >> 5;
    const int wpb = blockDim.x >> 5;

    float2 s = {0.f, 0.f}, q = {0.f, 0.f};
    for (int r = blockIdx.x * wpb + warp; r < n; r += gridDim.x * wpb) {
        float2 v = *(const float2*)(y + (size_t)r * 64 + 2 * lane);
        s.x += v.x; s.y += v.y;
        q.x = fmaf(v.x, v.x, q.x);
        q.y = fmaf(v.y, v.y, q.y);
    }
    __shared__ float2 sh_s[8][32], sh_q[8][32];
    sh_s[warp][lane] = s;
    sh_q[warp][lane] = q;
    __syncthreads();
    if (warp == 0) {
        for (int i = 1; i < wpb; i++) {
            s.x += sh_s[i][lane].x; s.y += sh_s[i][lane].y;
            q.x += sh_q[i][lane].x; q.y += sh_q[i][lane].y;
        }
        atomicAdd(&sums[lane], s);
        atomicAdd(&sums[32 + lane], q);
    }
}

__global__ void finalize_kernel(const float2* __restrict__ sums,
                                const float* __restrict__ gamma,
                                const float* __restrict__ beta,
                                float* __restrict__ bnout, float invN) {
    int l = threadIdx.x;  // 0..31 -> channels 2l, 2l+1
    float2 s = sums[l], q = sums[32 + l];
    float m0 = s.x * invN, m1 = s.y * invN;
    float v0 = fmaf(q.x, invN, -m0 * m0);
    float v1 = fmaf(q.y, invN, -m1 * m1);
    float sc0 = gamma[2 * l] * rsqrtf(v0 + 1e-5f);
    float sc1 = gamma[2 * l + 1] * rsqrtf(v1 + 1e-5f);
    bnout[2 * l] = sc0;
    bnout[2 * l + 1] = sc1;
    bnout[64 + 2 * l] = beta[2 * l] - m0 * sc0;
    bnout[64 + 2 * l + 1] = beta[2 * l + 1] - m1 * sc1;
}

// y1a = relu(bn1(y1))
__global__ __launch_bounds__(256) void apply_bn_kernel(const float4* __restrict__ y,
                                                       const float* __restrict__ bn,
                                                       float4* __restrict__ out, int n4) {
    int i = blockIdx.x * blockDim.x + threadIdx.x;
    if (i >= n4) return;
    int c4 = (i & 15) * 4;
    float4 v = y[i];
    float4 sc = *(const float4*)(bn + c4);
    float4 sh = *(const float4*)(bn + 64 + c4);
    float4 o;
    o.x = fmaxf(fmaf(v.x, sc.x, sh.x), 0.f);
    o.y = fmaxf(fmaf(v.y, sc.y, sh.y), 0.f);
    o.z = fmaxf(fmaf(v.z, sc.z, sh.z), 0.f);
    o.w = fmaxf(fmaf(v.w, sc.w, sh.w), 0.f);
    out[i] = o;
}

__global__ __launch_bounds__(256) void final_kernel(const float4* __restrict__ y2,
                                                    const float4* __restrict__ x,
                                                    const float* __restrict__ bn,
                                                    float4* __restrict__ out, int n4) {
    int i = blockIdx.x * blockDim.x + threadIdx.x;
    if (i >= n4) return;
    int c4 = (i & 15) * 4;
    float4 v = y2[i], xr = x[i];
    float4 sc = *(const float4*)(bn + c4);
    float4 sh = *(const float4*)(bn + 64 + c4);
    float4 o;
    o.x = fmaxf(fmaf(v.x, sc.x, sh.x) + xr.x, 0.f);
    o.y = fmaxf(fmaf(v.y, sc.y, sh.y) + xr.y, 0.f);
    o.z = fmaxf(fmaf(v.z, sc.z, sh.z) + xr.z, 0.f);
    o.w = fmaxf(fmaf(v.w, sc.w, sh.w) + xr.w, 0.f);
    out[i] = o;
}

// ---------------------------------------------------------------------------
extern "C" void kernel_launch(void* const* d_in, const int* in_sizes, int n_in,
                              void* d_out, int out_size) {
    const float* x      = (const float*)d_in[0];
    const float* W1     = (const float*)d_in[2];
    const float* gamma1 = (const float*)d_in[3];
    const float* beta1  = (const float*)d_in[4];
    const float* W2     = (const float*)d_in[5];
    const float* gamma2 = (const float*)d_in[6];
    const float* beta2  = (const float*)d_in[7];
    const int* in_idx   = (const int*)d_in[8];
    const int* out_idx  = (const int*)d_in[9];

    const int N = in_sizes[0] / 64;
    const int K = in_sizes[2] / (64 * 64);

    float *y1, *y1a, *y2, *bn;
    float2* stats;
    cudaGetSymbolAddress((void**)&y1, g_y1);
    cudaGetSymbolAddress((void**)&y1a, g_y1a);
    cudaGetSymbolAddress((void**)&y2, g_y2);
    cudaGetSymbolAddress((void**)&stats, g_stats);
    cudaGetSymbolAddress((void**)&bn, g_bn);

    cudaFuncSetAttribute(conv_mma_kernel,
                         cudaFuncAttributeMaxDynamicSharedMemorySize, SMEM_BYTES);

    cudaMemsetAsync(y1, 0, (size_t)N * 64 * sizeof(float));
    cudaMemsetAsync(y2, 0, (size_t)N * 64 * sizeof(float));
    cudaMemsetAsync(stats, 0, 4 * 32 * sizeof(float2));

    const int NB = 296;  // 2 CTAs per SM
    const float invN = 1.0f / (float)N;

    // layer 1
    conv_mma_kernel<<<NB, 256, SMEM_BYTES>>>(x, W1, in_idx, out_idx, y1, N, K, NB);
    stats_kernel<<<256, 256>>>(y1, stats, N);
    finalize_kernel<<<1, 32>>>(stats, gamma1, beta1, bn, invN);
    apply_bn_kernel<<<(N * 16 + 255) / 256, 256>>>((const float4*)y1, bn, (float4*)y1a, N * 16);

    // layer 2
    conv_mma_kernel<<<NB, 256, SMEM_BYTES>>>(y1a, W2, in_idx, out_idx, y2, N, K, NB);
    stats_kernel<<<256, 256>>>(y2, stats + 64, N);
    finalize_kernel<<<1, 32>>>(stats + 64, gamma2, beta2, bn + 128, invN);

    // epilogue
    final_kernel<<<(N * 16 + 255) / 256, 256>>>((const float4*)y2, (const float4*)x,
                                                bn + 128, (float4*)d_out, N * 16);
}

// round 7
// speedup vs baseline: 2.6636x; 1.2880x over previous
#include <cuda_runtime.h>
#include <cstdint>

// ============================================================================
// ResidualBlockWithPointsBase — mma.sync tf32 3-pass + cp.async.bulk gather
//   y1 = conv(x, W1); BN1 fold; y1a = relu(bn1(y1));
//   y2 = conv(y1a, W2); BN2 fold; out = relu(bn2(y2) + x)
// conv: persistent CTAs over (k, 128-edge tile):
//   double-buffered row gather via cp.async.bulk (256B/row, mbarrier
//   complete_tx) -> in-register tf32 hi/lo -> warp mma.m16n8k8 (3xTF32,
//   W in smem pad-68, column-permuted) -> red.global.add.v4.f32 scatter.
//   2 CTAs/SM.
// ============================================================================

#define MAXN 100352
typedef unsigned long long ull;

__device__ float g_y1[MAXN * 64];
__device__ float g_y1a[MAXN * 64];
__device__ float g_y2[MAXN * 64];
__device__ float2 g_stats[4 * 32];
__device__ float g_bn[4 * 64];

__device__ __forceinline__ float tf32_rna(float x) {
    float r;
    asm("cvt.rna.tf32.f32 %0, %1;" : "=f"(r) : "f"(x));
    return r;
}
__device__ __forceinline__ void mma_tf32(float* d, const uint32_t* a, const uint32_t* b) {
    asm volatile(
        "mma.sync.aligned.m16n8k8.row.col.f32.tf32.tf32.f32 "
        "{%0,%1,%2,%3}, {%4,%5,%6,%7}, {%8,%9}, {%0,%1,%2,%3};"
        : "+f"(d[0]), "+f"(d[1]), "+f"(d[2]), "+f"(d[3])
        : "r"(a[0]), "r"(a[1]), "r"(a[2]), "r"(a[3]), "r"(b[0]), "r"(b[1]));
}
__device__ __forceinline__ void red_add_v4(float* g, float a, float b, float c, float d) {
    asm volatile("red.global.add.v4.f32 [%0], {%1, %2, %3, %4};"
                 :: "l"(g), "f"(a), "f"(b), "f"(c), "f"(d) : "memory");
}

#define MBAR_WAIT(a, ph) do {                                                     \
    asm volatile("{\n\t.reg .pred P1;\n\tWL_%=:\n\t"                              \
        "mbarrier.try_wait.parity.acquire.cta.shared::cta.b64 P1, [%0], %1, 0x989680;\n\t" \
        "@P1 bra.uni WD_%=;\n\tbra.uni WL_%=;\n\tWD_%=:\n\t}"                     \
        :: "r"(a), "r"(ph) : "memory");                                           \
} while (0)

// smem float offsets
#define A_PAD 68
#define W_PAD 68
#define OFF_A0 0
#define OFF_A1 (128 * A_PAD)                 // 8704
#define OFF_WH (2 * 128 * A_PAD)             // 17408
#define OFF_WL (OFF_WH + 64 * W_PAD)         // 21760
#define OFF_MBAR (OFF_WL + 64 * W_PAD)       // 26112 (x4 = 104448, 8B aligned)
#define SMEM_FLOATS (OFF_MBAR + 4)
#define SMEM_BYTES (SMEM_FLOATS * 4)         // 104464

#define TILE_BYTES 32768u  // 128 rows x 256B

// ---------------------------------------------------------------------------
__global__ __launch_bounds__(256, 2) void conv_mma_kernel(
    const float* __restrict__ xin,  // [N][64]
    const float* __restrict__ W,    // [K][64][64]
    const int* __restrict__ in_idx, const int* __restrict__ out_idx,
    float* __restrict__ yout,       // [N][64] pre-zeroed
    int nE, int K, int nblk) {
    extern __shared__ float sm[];
    float* Wh = sm + OFF_WH;  // transposed, col-permuted: Wh[colP*W_PAD + row]
    float* Wl = sm + OFF_WL;
    const uint32_t smb = (uint32_t)__cvta_generic_to_shared(sm);

    const int tid = threadIdx.x;
    const int lane = tid & 31;
    const int wid = tid >> 5;
    const int gi = lane >> 2;
    const int tq = lane & 3;
    const int EB = (wid >> 1) * 32;    // warp's edge base
    const int NBASE = (wid & 1) * 32;  // warp's cout base

    const int tilesPerK = (nE + 127) >> 7;
    const int total = K * tilesPerK;
    const int chunk = (total + nblk - 1) / nblk;
    const int it0 = blockIdx.x * chunk;
    const int it1 = min(it0 + chunk, total);
    if (it0 >= it1) return;

    // mbarrier init (one per stage, arrive count 1)
    if (tid == 0) {
        asm volatile("mbarrier.init.shared.b64 [%0], 1;" :: "r"(smb + 4 * OFF_MBAR) : "memory");
        asm volatile("mbarrier.init.shared.b64 [%0], 1;" :: "r"(smb + 4 * OFF_MBAR + 8) : "memory");
        asm volatile("fence.proxy.async.shared::cta;" ::: "memory");
    }
    __syncthreads();

    // this thread's gather row index for a tile item (threads 0..127)
    auto load_idx = [&](int item) -> int {
        int k = item / tilesPerK;
        int e = (item - k * tilesPerK) * 128 + tid;
        return (e < nE) ? __ldg(in_idx + (size_t)k * nE + e) : 0;
    };
    // issue bulk gather of tile `item` into stage (item&1)
    auto issue = [&](int item, int src_row) {
        const uint32_t st = (uint32_t)(item & 1);
        const uint32_t mb = smb + 4 * OFF_MBAR + 8 * st;
        if (tid == 0)
            asm volatile("mbarrier.arrive.expect_tx.shared.b64 _, [%0], %1;"
                         :: "r"(mb), "r"(TILE_BYTES) : "memory");
        if (tid < 128) {
            const float* src = xin + (size_t)src_row * 64;
            uint32_t dst = smb + 4 * (st ? OFF_A1 : OFF_A0) + (uint32_t)tid * (A_PAD * 4);
            asm volatile(
                "cp.async.bulk.shared::cluster.global.mbarrier::complete_tx::bytes "
                "[%0], [%1], %2, [%3];"
                :: "r"(dst), "l"(src), "r"(256u), "r"(mb) : "memory");
        }
    };

    int cur_k = -1;
    uint32_t ph0 = 0, ph1 = 0;

    int nidx = (tid < 128) ? load_idx(it0) : 0;
    issue(it0, nidx);
    nidx = (tid < 128 && it0 + 1 < it1) ? load_idx(it0 + 1) : 0;

    for (int item = it0; item < it1; item++) {
        const int k = item / tilesPerK;
        const int tile = item - k * tilesPerK;
        const int ebase = tile * 128;
        const int st = item & 1;

        if (item + 1 < it1) {
            issue(item + 1, nidx);
            nidx = (tid < 128 && item + 2 < it1) ? load_idx(item + 2) : 0;
        }

        if (k != cur_k) {  // W restage (prev readers done via prev-iter syncthreads)
            cur_k = k;
            const float* Wk = W + (size_t)k * 4096;
            for (int i = tid; i < 4096; i += 256) {
                int row = i >> 6, colP = i & 63;
                int l16 = colP & 15;
                // inverse column permutation (for v4 scatter)
                int Lcol = (colP & ~15) + 4 * ((l16 >> 1) & 3) + 2 * ((l16 >> 3) & 1) + (l16 & 1);
                float w = __ldg(Wk + (size_t)row * 64 + Lcol);
                float hh = tf32_rna(w);
                Wh[colP * W_PAD + row] = hh;
                Wl[colP * W_PAD + row] = tf32_rna(w - hh);
            }
            __syncthreads();
        }

        // wait for tile's gather to land
        MBAR_WAIT(smb + 4 * OFF_MBAR + 8 * st, st ? ph1 : ph0);
        if (st) ph1 ^= 1; else ph0 ^= 1;

        const float* Abuf = sm + (st ? OFF_A1 : OFF_A0);

        // ---- compute: 2 m-tiles x 4 n-tiles, 8 k-chunks, 3 passes ----
        float acc[2][4][4];
#pragma unroll
        for (int mt = 0; mt < 2; mt++)
#pragma unroll
            for (int nt = 0; nt < 4; nt++)
#pragma unroll
                for (int r = 0; r < 4; r++) acc[mt][nt][r] = 0.f;

#pragma unroll
        for (int kc = 0; kc < 8; kc++) {
            uint32_t ah[2][4], al[2][4];
#pragma unroll
            for (int mt = 0; mt < 2; mt++) {
                const float* p = Abuf + (EB + mt * 16 + gi) * A_PAD + kc * 8 + tq;
                float r0 = p[0], r1 = p[8 * A_PAD], r2 = p[4], r3 = p[8 * A_PAD + 4];
                float h0 = tf32_rna(r0), h1 = tf32_rna(r1);
                float h2 = tf32_rna(r2), h3 = tf32_rna(r3);
                ah[mt][0] = __float_as_uint(h0);
                ah[mt][1] = __float_as_uint(h1);
                ah[mt][2] = __float_as_uint(h2);
                ah[mt][3] = __float_as_uint(h3);
                al[mt][0] = __float_as_uint(tf32_rna(r0 - h0));
                al[mt][1] = __float_as_uint(tf32_rna(r1 - h1));
                al[mt][2] = __float_as_uint(tf32_rna(r2 - h2));
                al[mt][3] = __float_as_uint(tf32_rna(r3 - h3));
            }
#pragma unroll
            for (int nt = 0; nt < 4; nt++) {
                const int col = NBASE + nt * 8 + gi;
                const float* wp = Wh + col * W_PAD + kc * 8 + tq;
                const float* wq = Wl + col * W_PAD + kc * 8 + tq;
                uint32_t bh[2], bl[2];
                bh[0] = __float_as_uint(wp[0]);
                bh[1] = __float_as_uint(wp[4]);
                bl[0] = __float_as_uint(wq[0]);
                bl[1] = __float_as_uint(wq[4]);
#pragma unroll
                for (int mt = 0; mt < 2; mt++) {
                    mma_tf32(acc[mt][nt], ah[mt], bh);
                    mma_tf32(acc[mt][nt], al[mt], bh);
                    mma_tf32(acc[mt][nt], ah[mt], bl);
                }
            }
        }

        // ---- scatter: thread owns logical couts NBASE+16p+4tq..+3 (v4) ----
        const int* oi = out_idx + (size_t)k * nE + ebase;
#pragma unroll
        for (int mt = 0; mt < 2; mt++) {
            const int r0 = EB + mt * 16 + gi;
            const int og0 = (ebase + r0 < nE) ? __ldg(oi + r0) : -1;
            const int og1 = (ebase + r0 + 8 < nE) ? __ldg(oi + r0 + 8) : -1;
#pragma unroll
            for (int p = 0; p < 2; p++) {
                const int cbase = NBASE + 16 * p + 4 * tq;
                if (og0 >= 0)
                    red_add_v4(yout + (size_t)og0 * 64 + cbase,
                               acc[mt][2 * p][0], acc[mt][2 * p][1],
                               acc[mt][2 * p + 1][0], acc[mt][2 * p + 1][1]);
                if (og1 >= 0)
                    red_add_v4(yout + (size_t)og1 * 64 + cbase,
                               acc[mt][2 * p][2], acc[mt][2 * p][3],
                               acc[mt][2 * p + 1][2], acc[mt][2 * p + 1][3]);
            }
        }
        __syncthreads();  // all reads of stage st done -> safe to re-issue into it
    }
}

// ---------------------------------------------------------------------------
__global__ __launch_bounds__(256) void stats_kernel(const float* __restrict__ y,
                                                    float2* __restrict__ sums, int n) {
    const int lane = threadIdx.x & 31;
    const int warp = threadIdx.x >> 5;
    const int wpb = blockDim.x >> 5;

    float2 s = {0.f, 0.f}, q = {0.f, 0.f};
    for (int r = blockIdx.x * wpb + warp; r < n; r += gridDim.x * wpb) {
        float2 v = *(const float2*)(y + (size_t)r * 64 + 2 * lane);
        s.x += v.x; s.y += v.y;
        q.x = fmaf(v.x, v.x, q.x);
        q.y = fmaf(v.y, v.y, q.y);
    }
    __shared__ float2 sh_s[8][32], sh_q[8][32];
    sh_s[warp][lane] = s;
    sh_q[warp][lane] = q;
    __syncthreads();
    if (warp == 0) {
        for (int i = 1; i < wpb; i++) {
            s.x += sh_s[i][lane].x; s.y += sh_s[i][lane].y;
            q.x += sh_q[i][lane].x; q.y += sh_q[i][lane].y;
        }
        atomicAdd(&sums[lane], s);
        atomicAdd(&sums[32 + lane], q);
    }
}

__global__ void finalize_kernel(const float2* __restrict__ sums,
                                const float* __restrict__ gamma,
                                const float* __restrict__ beta,
                                float* __restrict__ bnout, float invN) {
    int l = threadIdx.x;  // 0..31 -> channels 2l, 2l+1
    float2 s = sums[l], q = sums[32 + l];
    float m0 = s.x * invN, m1 = s.y * invN;
    float v0 = fmaf(q.x, invN, -m0 * m0);
    float v1 = fmaf(q.y, invN, -m1 * m1);
    float sc0 = gamma[2 * l] * rsqrtf(v0 + 1e-5f);
    float sc1 = gamma[2 * l + 1] * rsqrtf(v1 + 1e-5f);
    bnout[2 * l] = sc0;
    bnout[2 * l + 1] = sc1;
    bnout[64 + 2 * l] = beta[2 * l] - m0 * sc0;
    bnout[64 + 2 * l + 1] = beta[2 * l + 1] - m1 * sc1;
}

// y1a = relu(bn1(y1))
__global__ __launch_bounds__(256) void apply_bn_kernel(const float4* __restrict__ y,
                                                       const float* __restrict__ bn,
                                                       float4* __restrict__ out, int n4) {
    int i = blockIdx.x * blockDim.x + threadIdx.x;
    if (i >= n4) return;
    int c4 = (i & 15) * 4;
    float4 v = y[i];
    float4 sc = *(const float4*)(bn + c4);
    float4 sh = *(const float4*)(bn + 64 + c4);
    float4 o;
    o.x = fmaxf(fmaf(v.x, sc.x, sh.x), 0.f);
    o.y = fmaxf(fmaf(v.y, sc.y, sh.y), 0.f);
    o.z = fmaxf(fmaf(v.z, sc.z, sh.z), 0.f);
    o.w = fmaxf(fmaf(v.w, sc.w, sh.w), 0.f);
    out[i] = o;
}

__global__ __launch_bounds__(256) void final_kernel(const float4* __restrict__ y2,
                                                    const float4* __restrict__ x,
                                                    const float* __restrict__ bn,
                                                    float4* __restrict__ out, int n4) {
    int i = blockIdx.x * blockDim.x + threadIdx.x;
    if (i >= n4) return;
    int c4 = (i & 15) * 4;
    float4 v = y2[i], xr = x[i];
    float4 sc = *(const float4*)(bn + c4);
    float4 sh = *(const float4*)(bn + 64 + c4);
    float4 o;
    o.x = fmaxf(fmaf(v.x, sc.x, sh.x) + xr.x, 0.f);
    o.y = fmaxf(fmaf(v.y, sc.y, sh.y) + xr.y, 0.f);
    o.z = fmaxf(fmaf(v.z, sc.z, sh.z) + xr.z, 0.f);
    o.w = fmaxf(fmaf(v.w, sc.w, sh.w) + xr.w, 0.f);
    out[i] = o;
}

// ---------------------------------------------------------------------------
extern "C" void kernel_launch(void* const* d_in, const int* in_sizes, int n_in,
                              void* d_out, int out_size) {
    const float* x      = (const float*)d_in[0];
    const float* W1     = (const float*)d_in[2];
    const float* gamma1 = (const float*)d_in[3];
    const float* beta1  = (const float*)d_in[4];
    const float* W2     = (const float*)d_in[5];
    const float* gamma2 = (const float*)d_in[6];
    const float* beta2  = (const float*)d_in[7];
    const int* in_idx   = (const int*)d_in[8];
    const int* out_idx  = (const int*)d_in[9];

    const int N = in_sizes[0] / 64;
    const int K = in_sizes[2] / (64 * 64);

    float *y1, *y1a, *y2, *bn;
    float2* stats;
    cudaGetSymbolAddress((void**)&y1, g_y1);
    cudaGetSymbolAddress((void**)&y1a, g_y1a);
    cudaGetSymbolAddress((void**)&y2, g_y2);
    cudaGetSymbolAddress((void**)&stats, g_stats);
    cudaGetSymbolAddress((void**)&bn, g_bn);

    cudaFuncSetAttribute(conv_mma_kernel,
                         cudaFuncAttributeMaxDynamicSharedMemorySize, SMEM_BYTES);

    cudaMemsetAsync(y1, 0, (size_t)N * 64 * sizeof(float));
    cudaMemsetAsync(y2, 0, (size_t)N * 64 * sizeof(float));
    cudaMemsetAsync(stats, 0, 4 * 32 * sizeof(float2));

    const int NB = 296;  // 2 CTAs per SM
    const float invN = 1.0f / (float)N;

    // layer 1
    conv_mma_kernel<<<NB, 256, SMEM_BYTES>>>(x, W1, in_idx, out_idx, y1, N, K, NB);
    stats_kernel<<<256, 256>>>(y1, stats, N);
    finalize_kernel<<<1, 32>>>(stats, gamma1, beta1, bn, invN);
    apply_bn_kernel<<<(N * 16 + 255) / 256, 256>>>((const float4*)y1, bn, (float4*)y1a, N * 16);

    // layer 2
    conv_mma_kernel<<<NB, 256, SMEM_BYTES>>>(y1a, W2, in_idx, out_idx, y2, N, K, NB);
    stats_kernel<<<256, 256>>>(y2, stats + 64, N);
    finalize_kernel<<<1, 32>>>(stats + 64, gamma2, beta2, bn + 128, invN);

    // epilogue
    final_kernel<<<(N * 16 + 255) / 256, 256>>>((const float4*)y2, (const float4*)x,
                                                bn + 128, (float4*)d_out, N * 16);
}